// round 1
// baseline (speedup 1.0000x reference)
#include <cuda_runtime.h>

// Problem constants
#define N_CB   8
#define VOCAB  1024
#define CDIM   16
#define BATCH  8
#define HW     1024          // 32*32
#define DCH    128           // N_CB*CDIM
#define BHW    8192          // BATCH*HW

// Output layout (float32, outputs concatenated flat in reference order)
#define OFF_Q      0           // quantized: 8*128*32*32 = 1048576
#define OFF_IDX    1048576     // indices:   8*8*32*32   = 65536
#define OFF_COMMIT 1114112     // commitment: 1
#define OFF_NCB    1114113     // new_codebooks: 8*1024*16 = 131072
#define OFF_NCNT   1245185     // new_count: 8*1024 = 8192
#define OFF_NW     1253377     // new_weight: 8*1024*16 = 131072
// total = 1384449

#define DECAY_F 0.99f
#define ALPHA_F 0.01f
#define EPS_F   1e-5f

// ---------- f32x2 packed helpers ----------
static __device__ __forceinline__ unsigned long long pack2(float lo, float hi) {
    unsigned long long r;
    asm("mov.b64 %0, {%1,%2};" : "=l"(r) : "f"(lo), "f"(hi));
    return r;
}
static __device__ __forceinline__ void unpack2(unsigned long long v, float& lo, float& hi) {
    asm("mov.b64 {%0,%1}, %2;" : "=f"(lo), "=f"(hi) : "l"(v));
}
static __device__ __forceinline__ unsigned long long fma2(unsigned long long a,
                                                          unsigned long long b,
                                                          unsigned long long c) {
    unsigned long long d;
    asm("fma.rn.f32x2 %0, %1, %2, %3;" : "=l"(d) : "l"(a), "l"(b), "l"(c));
    return d;
}

// ---------- kernel 1: initialize EMA output regions ----------
__global__ void vq_init(const float* __restrict__ ema_count,
                        const float* __restrict__ ema_weight,
                        float* __restrict__ out) {
    int i = blockIdx.x * blockDim.x + threadIdx.x;
    if (i == 0) out[OFF_COMMIT] = 0.0f;
    if (i < N_CB * VOCAB) out[OFF_NCNT + i] = DECAY_F * ema_count[i];
    if (i < N_CB * VOCAB * CDIM) out[OFF_NW + i] = DECAY_F * ema_weight[i];
}

// ---------- kernel 2: distances + argmin + outputs + scatter ----------
// grid: (32, 8)  -> blockIdx.y = codebook, blockIdx.x = chunk of 256 positions
// block: 128 threads, 2 positions per thread
__global__ __launch_bounds__(128) void vq_main(const float* __restrict__ z,
                                               const float* __restrict__ cbs,
                                               float* out) {
    extern __shared__ float sm[];
    float* cb_s = sm;                 // 16384 floats (one codebook, 64 KB)
    float* h_s  = sm + VOCAB * CDIM;  // 1024 floats (0.5*||c||^2)

    const int cb  = blockIdx.y;
    const int tid = threadIdx.x;

    // Load codebook slice into SMEM (coalesced float4)
    {
        const float4* src = (const float4*)(cbs + (size_t)cb * VOCAB * CDIM);
        float4* dst = (float4*)cb_s;
        #pragma unroll
        for (int i = 0; i < 32; i++) dst[tid + i * 128] = src[tid + i * 128];
    }
    __syncthreads();

    // Precompute h[v] = 0.5 * ||c_v||^2
    for (int v = tid; v < VOCAB; v += 128) {
        const float* r = cb_s + v * CDIM;
        float s = 0.0f;
        #pragma unroll
        for (int j = 0; j < CDIM; j++) s += r[j] * r[j];
        h_s[v] = 0.5f * s;
    }
    __syncthreads();

    // Two positions per thread
    const int p0  = blockIdx.x * 256 + tid;
    const int p1  = p0 + 128;
    const int b   = p0 >> 10;            // same for p0/p1 (chunk aligned)
    const int hw0 = p0 & (HW - 1);
    const int hw1 = p1 & (HW - 1);

    const float* zb = z + (size_t)b * DCH * HW + (size_t)cb * CDIM * HW;

    float z0f[CDIM], z1f[CDIM];
    #pragma unroll
    for (int j = 0; j < CDIM; j++) {
        z0f[j] = zb[j * HW + hw0];
        z1f[j] = zb[j * HW + hw1];
    }

    unsigned long long nz0[8], nz1[8];
    #pragma unroll
    for (int k = 0; k < 8; k++) {
        nz0[k] = pack2(-z0f[2 * k], -z0f[2 * k + 1]);
        nz1[k] = pack2(-z1f[2 * k], -z1f[2 * k + 1]);
    }

    // Argmin sweep: score(v) = 0.5||c||^2 - z.c  (packed f32x2 over dim pairs)
    float best0 = 3.0e38f, best1 = 3.0e38f;
    int bi0 = 0, bi1 = 0;
    const unsigned long long* cb2 = (const unsigned long long*)cb_s;

    #pragma unroll 2
    for (int v = 0; v < VOCAB; v++) {
        const unsigned long long* row = cb2 + v * 8;
        unsigned long long a0 = 0ull, a1 = 0ull;
        #pragma unroll
        for (int k = 0; k < 8; k++) {
            unsigned long long c = row[k];
            a0 = fma2(nz0[k], c, a0);
            a1 = fma2(nz1[k], c, a1);
        }
        float l0, u0, l1, u1;
        unpack2(a0, l0, u0);
        unpack2(a1, l1, u1);
        const float hv = h_s[v];
        const float s0 = hv + (l0 + u0);
        const float s1 = hv + (l1 + u1);
        if (s0 < best0) { best0 = s0; bi0 = v; }
        if (s1 < best1) { best1 = s1; bi1 = v; }
    }

    // ------------- epilogue -------------
    float* qout    = out + OFF_Q;
    float* idxout  = out + OFF_IDX;
    float* ncount  = out + OFF_NCNT;
    float* nweight = out + OFF_NW;

    float locc = 0.0f;

    // position 0
    {
        const float* crow = cb_s + bi0 * CDIM;
        const size_t qbase = (size_t)b * DCH * HW + (size_t)cb * CDIM * HW + hw0;
        float* wdst = nweight + ((size_t)cb * VOCAB + bi0) * CDIM;
        #pragma unroll
        for (int j = 0; j < CDIM; j++) {
            const float zj = z0f[j];
            const float cj = crow[j];
            qout[qbase + (size_t)j * HW] = zj + (cj - zj);   // match zq_st rounding
            const float d = zj - cj;
            locc += d * d;
            atomicAdd(&wdst[j], ALPHA_F * zj);
        }
        idxout[(size_t)b * (N_CB * HW) + (size_t)cb * HW + hw0] = (float)bi0;
        atomicAdd(&ncount[cb * VOCAB + bi0], ALPHA_F);
    }
    // position 1
    {
        const float* crow = cb_s + bi1 * CDIM;
        const size_t qbase = (size_t)b * DCH * HW + (size_t)cb * CDIM * HW + hw1;
        float* wdst = nweight + ((size_t)cb * VOCAB + bi1) * CDIM;
        #pragma unroll
        for (int j = 0; j < CDIM; j++) {
            const float zj = z1f[j];
            const float cj = crow[j];
            qout[qbase + (size_t)j * HW] = zj + (cj - zj);
            const float d = zj - cj;
            locc += d * d;
            atomicAdd(&wdst[j], ALPHA_F * zj);
        }
        idxout[(size_t)b * (N_CB * HW) + (size_t)cb * HW + hw1] = (float)bi1;
        atomicAdd(&ncount[cb * VOCAB + bi1], ALPHA_F);
    }

    // commitment: block reduce -> 1 atomic per block
    __shared__ float red[128];
    red[tid] = locc;
    __syncthreads();
    #pragma unroll
    for (int st = 64; st > 0; st >>= 1) {
        if (tid < st) red[tid] += red[tid + st];
        __syncthreads();
    }
    if (tid == 0) {
        atomicAdd(out + OFF_COMMIT, red[0] * (1.0f / (float)(BHW * N_CB * CDIM)));
    }
}

// ---------- kernel 3: normalized codebook update ----------
// grid: 8 blocks (one per codebook), 1024 threads (one per vocab entry)
__global__ __launch_bounds__(1024) void vq_final(float* out) {
    const int cb = blockIdx.x;
    const int v  = threadIdx.x;

    const float cnt = out[OFF_NCNT + cb * VOCAB + v];

    __shared__ float s[1024];
    s[v] = cnt;
    __syncthreads();
    #pragma unroll
    for (int st = 512; st > 0; st >>= 1) {
        if (v < st) s[v] += s[v + st];
        __syncthreads();
    }
    const float n = s[0];
    const float countv = (cnt + EPS_F) / (n + VOCAB * EPS_F) * n;

    const float* w = out + OFF_NW  + ((size_t)cb * VOCAB + v) * CDIM;
    float*       o = out + OFF_NCB + ((size_t)cb * VOCAB + v) * CDIM;
    #pragma unroll
    for (int j = 0; j < CDIM; j++) o[j] = w[j] / countv;
}

extern "C" void kernel_launch(void* const* d_in, const int* in_sizes, int n_in,
                              void* d_out, int out_size) {
    const float* z   = (const float*)d_in[0];
    const float* cbs = (const float*)d_in[1];
    const float* ec  = (const float*)d_in[2];
    const float* ew  = (const float*)d_in[3];
    float* out = (float*)d_out;

    const size_t smem = (size_t)(VOCAB * CDIM + VOCAB) * sizeof(float); // 69632 B
    cudaFuncSetAttribute(vq_main, cudaFuncAttributeMaxDynamicSharedMemorySize, (int)smem);

    vq_init<<<512, 256>>>(ec, ew, out);
    dim3 grid(32, N_CB);
    vq_main<<<grid, 128, smem>>>(z, cbs, out);
    vq_final<<<N_CB, 1024>>>(out);
}

// round 2
// speedup vs baseline: 1.0859x; 1.0859x over previous
#include <cuda_runtime.h>

// Problem constants
#define N_CB   8
#define VOCAB  1024
#define VHALF  512
#define PAIRS  256          // vocab pairs per block
#define CDIM   16
#define BATCH  8
#define HW     1024         // 32*32
#define DCH    128          // N_CB*CDIM
#define BHW    8192         // BATCH*HW
#define NITEMS 65536        // BHW * N_CB

// Output layout (float32, concatenated flat in reference order)
#define OFF_Q      0
#define OFF_IDX    1048576
#define OFF_COMMIT 1114112
#define OFF_NCB    1114113
#define OFF_NCNT   1245185
#define OFF_NW     1253377

#define DECAY_F 0.99f
#define ALPHA_F 0.01f
#define EPS_F   1e-5f

// cross-block argmin scratch: (monotone score bits << 32) | global vocab idx
__device__ unsigned long long vq_scratch[NITEMS];

// ---------- f32x2 packed helpers ----------
static __device__ __forceinline__ unsigned long long pack2(float lo, float hi) {
    unsigned long long r;
    asm("mov.b64 %0, {%1,%2};" : "=l"(r) : "f"(lo), "f"(hi));
    return r;
}
static __device__ __forceinline__ void unpack2(unsigned long long v, float& lo, float& hi) {
    asm("mov.b64 {%0,%1}, %2;" : "=f"(lo), "=f"(hi) : "l"(v));
}
static __device__ __forceinline__ unsigned long long fma2(unsigned long long a,
                                                          unsigned long long b,
                                                          unsigned long long c) {
    unsigned long long d;
    asm("fma.rn.f32x2 %0, %1, %2, %3;" : "=l"(d) : "l"(a), "l"(b), "l"(c));
    return d;
}
// monotone float -> u32 (order-preserving for all finite floats)
static __device__ __forceinline__ unsigned int fkey(float s) {
    unsigned int b = __float_as_uint(s);
    return (b & 0x80000000u) ? ~b : (b | 0x80000000u);
}

// ---------- kernel 1: init EMA outputs + scratch ----------
__global__ void vq_init(const float* __restrict__ ema_count,
                        const float* __restrict__ ema_weight,
                        float* __restrict__ out) {
    int i = blockIdx.x * blockDim.x + threadIdx.x;
    if (i == 0) out[OFF_COMMIT] = 0.0f;
    if (i < N_CB * VOCAB) out[OFF_NCNT + i] = DECAY_F * ema_count[i];
    if (i < N_CB * VOCAB * CDIM) out[OFF_NW + i] = DECAY_F * ema_weight[i];
    if (i < NITEMS) vq_scratch[i] = 0xFFFFFFFFFFFFFFFFull;
}

// ---------- kernel 2: distance sweep + argmin (vocab-split) ----------
// grid: (32, 8, 2) -> x: chunk of 256 positions, y: codebook, z: vocab half
// block: 128 threads, 2 positions per thread
// smem row layout per vocab pair p: 16 u64 of (c[2p][j], c[2p+1][j]) then
// 1 u64 of (0.5||c_2p||^2, 0.5||c_2p+1||^2)  -> 17 u64 = 34 floats
__global__ __launch_bounds__(128) void vq_main(const float* __restrict__ z,
                                               const float* __restrict__ cbs) {
    __shared__ float sm[PAIRS * 34];   // 34816 B

    const int cb    = blockIdx.y;
    const int vbase = blockIdx.z * VHALF;
    const int tid   = threadIdx.x;

    // Load this block's half-codebook, interleaving vocab pairs
    {
        const float* src = cbs + ((size_t)cb * VOCAB + vbase) * CDIM;  // 8192 floats
        #pragma unroll
        for (int t = 0; t < 64; t++) {
            int i = tid + t * 128;            // coalesced read
            int v = i >> 4, j = i & 15;
            sm[(v >> 1) * 34 + 2 * j + (v & 1)] = src[i];
        }
    }
    __syncthreads();
    // h pairs
    #pragma unroll
    for (int t = 0; t < 4; t++) {
        int v = tid + t * 128;
        int p = v >> 1, o = v & 1;
        const float* r = sm + p * 34 + o;
        float s = 0.0f;
        #pragma unroll
        for (int j = 0; j < CDIM; j++) { float c = r[2 * j]; s += c * c; }
        sm[p * 34 + 32 + o] = 0.5f * s;
    }
    __syncthreads();

    // two positions per thread
    const int p0  = blockIdx.x * 256 + tid;
    const int p1  = p0 + 128;
    const int b   = p0 >> 10;
    const int hw0 = p0 & (HW - 1);
    const int hw1 = p1 & (HW - 1);

    const float* zb = z + (size_t)b * DCH * HW + (size_t)cb * CDIM * HW;

    unsigned long long zz0[CDIM], zz1[CDIM];
    #pragma unroll
    for (int j = 0; j < CDIM; j++) {
        float a = zb[j * HW + hw0];
        float c = zb[j * HW + hw1];
        zz0[j] = pack2(-a, -a);
        zz1[j] = pack2(-c, -c);
    }

    float best0 = 3.0e38f, best1 = 3.0e38f;
    int   bi0 = 0, bi1 = 0;
    const unsigned long long* base = (const unsigned long long*)sm;

    #pragma unroll 2
    for (int p = 0; p < PAIRS; p++) {
        const unsigned long long* row = base + p * 17;
        const unsigned long long h = row[16];
        unsigned long long a0 = fma2(zz0[0], row[0], h);
        unsigned long long a1 = fma2(zz1[0], row[0], h);
        #pragma unroll
        for (int k = 1; k < CDIM; k++) {
            unsigned long long c = row[k];
            a0 = fma2(zz0[k], c, a0);
            a1 = fma2(zz1[k], c, a1);
        }
        float sv0, sw0, sv1, sw1;
        unpack2(a0, sv0, sw0);
        unpack2(a1, sv1, sw1);
        const int ve = 2 * p, vo = 2 * p + 1;
        bool t;
        t = sv0 < best0; best0 = t ? sv0 : best0; bi0 = t ? ve : bi0;
        t = sw0 < best0; best0 = t ? sw0 : best0; bi0 = t ? vo : bi0;
        t = sv1 < best1; best1 = t ? sv1 : best1; bi1 = t ? ve : bi1;
        t = sw1 < best1; best1 = t ? sw1 : best1; bi1 = t ? vo : bi1;
    }

    // combine across vocab halves (ties -> smaller idx, matching argmin)
    unsigned long long* sc = vq_scratch + (size_t)cb * BHW;
    atomicMin(&sc[p0], ((unsigned long long)fkey(best0) << 32) | (unsigned)(vbase + bi0));
    atomicMin(&sc[p1], ((unsigned long long)fkey(best1) << 32) | (unsigned)(vbase + bi1));
}

// ---------- kernel 3: epilogue (quantize, indices, scatter, commitment) ----------
// grid: (64, 8), block 128, one position per thread
__global__ __launch_bounds__(128) void vq_epi(const float* __restrict__ z,
                                              const float* __restrict__ cbs,
                                              float* out) {
    const int cb  = blockIdx.y;
    const int tid = threadIdx.x;
    const int pos = blockIdx.x * 128 + tid;
    const int b   = pos >> 10;
    const int hw  = pos & (HW - 1);

    const int bi = (int)(unsigned)vq_scratch[(size_t)cb * BHW + pos];

    const float* crow = cbs + ((size_t)cb * VOCAB + bi) * CDIM;
    const float* zb   = z + (size_t)b * DCH * HW + (size_t)cb * CDIM * HW + hw;

    float* qout    = out + OFF_Q + (size_t)b * DCH * HW + (size_t)cb * CDIM * HW + hw;
    float* nweight = out + OFF_NW + ((size_t)cb * VOCAB + bi) * CDIM;

    float locc = 0.0f;
    #pragma unroll
    for (int j = 0; j < CDIM; j++) {
        const float zj = zb[(size_t)j * HW];
        const float cj = crow[j];
        qout[(size_t)j * HW] = zj + (cj - zj);       // match zq_st rounding
        const float d = zj - cj;
        locc += d * d;
        atomicAdd(&nweight[j], ALPHA_F * zj);
    }
    out[OFF_IDX + (size_t)b * (N_CB * HW) + (size_t)cb * HW + hw] = (float)bi;
    atomicAdd(out + OFF_NCNT + cb * VOCAB + bi, ALPHA_F);

    __shared__ float red[128];
    red[tid] = locc;
    __syncthreads();
    #pragma unroll
    for (int st = 64; st > 0; st >>= 1) {
        if (tid < st) red[tid] += red[tid + st];
        __syncthreads();
    }
    if (tid == 0)
        atomicAdd(out + OFF_COMMIT, red[0] * (1.0f / (float)(BHW * N_CB * CDIM)));
}

// ---------- kernel 4: normalized codebook update ----------
__global__ __launch_bounds__(1024) void vq_final(float* out) {
    const int cb = blockIdx.x;
    const int v  = threadIdx.x;

    const float cnt = out[OFF_NCNT + cb * VOCAB + v];

    __shared__ float s[1024];
    s[v] = cnt;
    __syncthreads();
    #pragma unroll
    for (int st = 512; st > 0; st >>= 1) {
        if (v < st) s[v] += s[v + st];
        __syncthreads();
    }
    const float n = s[0];
    const float countv = (cnt + EPS_F) / (n + VOCAB * EPS_F) * n;

    const float* w = out + OFF_NW  + ((size_t)cb * VOCAB + v) * CDIM;
    float*       o = out + OFF_NCB + ((size_t)cb * VOCAB + v) * CDIM;
    #pragma unroll
    for (int j = 0; j < CDIM; j++) o[j] = w[j] / countv;
}

extern "C" void kernel_launch(void* const* d_in, const int* in_sizes, int n_in,
                              void* d_out, int out_size) {
    const float* z   = (const float*)d_in[0];
    const float* cbs = (const float*)d_in[1];
    const float* ec  = (const float*)d_in[2];
    const float* ew  = (const float*)d_in[3];
    float* out = (float*)d_out;

    vq_init<<<512, 256>>>(ec, ew, out);
    dim3 gmain(32, N_CB, 2);
    vq_main<<<gmain, 128>>>(z, cbs);
    dim3 gepi(64, N_CB);
    vq_epi<<<gepi, 128>>>(z, cbs, out);
    vq_final<<<N_CB, 1024>>>(out);
}

// round 3
// speedup vs baseline: 1.2519x; 1.1529x over previous
#include <cuda_runtime.h>

// Problem constants
#define N_CB   8
#define VOCAB  1024
#define VHALF  512
#define PAIRS  256          // vocab pairs per block
#define CDIM   16
#define BATCH  8
#define HW     1024         // 32*32
#define DCH    128          // N_CB*CDIM
#define BHW    8192         // BATCH*HW
#define NITEMS 65536        // BHW * N_CB

// Output layout (float32, concatenated flat in reference order)
#define OFF_Q      0
#define OFF_IDX    1048576
#define OFF_COMMIT 1114112
#define OFF_NCB    1114113
#define OFF_NCNT   1245185
#define OFF_NW     1253377

#define DECAY_F 0.99f
#define ALPHA_F 0.01f
#define EPS_F   1e-5f

// cross-block argmin scratch: (monotone score bits << 32) | global vocab idx
__device__ unsigned long long vq_scratch[NITEMS];
// per-codebook n = sum(new_count) (computed analytically in vq_init)
__device__ float n_dev[N_CB];

// ---------- f32x2 packed helpers ----------
static __device__ __forceinline__ unsigned long long pack2(float lo, float hi) {
    unsigned long long r;
    asm("mov.b64 %0, {%1,%2};" : "=l"(r) : "f"(lo), "f"(hi));
    return r;
}
static __device__ __forceinline__ void unpack2(unsigned long long v, float& lo, float& hi) {
    asm("mov.b64 {%0,%1}, %2;" : "=f"(lo), "=f"(hi) : "l"(v));
}
static __device__ __forceinline__ unsigned long long fma2(unsigned long long a,
                                                          unsigned long long b,
                                                          unsigned long long c) {
    unsigned long long d;
    asm("fma.rn.f32x2 %0, %1, %2, %3;" : "=l"(d) : "l"(a), "l"(b), "l"(c));
    return d;
}
// monotone float -> u32 (order-preserving for all finite floats)
static __device__ __forceinline__ unsigned int fkey(float s) {
    unsigned int b = __float_as_uint(s);
    return (b & 0x80000000u) ? ~b : (b | 0x80000000u);
}

// ---------- kernel 1: init EMA outputs + scratch + per-cb n ----------
// grid 512 x 256
__global__ void vq_init(const float* __restrict__ ema_count,
                        const float* __restrict__ ema_weight,
                        float* __restrict__ out) {
    const int tid = threadIdx.x;
    const int i = blockIdx.x * blockDim.x + tid;
    if (i == 0) out[OFF_COMMIT] = 0.0f;
    if (i < N_CB * VOCAB) out[OFF_NCNT + i] = DECAY_F * ema_count[i];
    if (i < N_CB * VOCAB * CDIM) out[OFF_NW + i] = DECAY_F * ema_weight[i];
    if (i < NITEMS) vq_scratch[i] = 0xFFFFFFFFFFFFFFFFull;

    // block 0 additionally computes n[cb] = 0.99*sum(ema_count[cb]) + 0.01*BHW
    if (blockIdx.x == 0) {
        __shared__ float red[8][8];   // [cb][warp]
        const int lane = tid & 31;
        const int wrp  = tid >> 5;    // 0..7
        #pragma unroll
        for (int cb = 0; cb < N_CB; cb++) {
            float s = ema_count[cb * VOCAB + tid]
                    + ema_count[cb * VOCAB + tid + 256]
                    + ema_count[cb * VOCAB + tid + 512]
                    + ema_count[cb * VOCAB + tid + 768];
            #pragma unroll
            for (int st = 16; st > 0; st >>= 1)
                s += __shfl_xor_sync(0xFFFFFFFFu, s, st);
            if (lane == 0) red[cb][wrp] = s;
        }
        __syncthreads();
        if (tid < N_CB) {
            float s = 0.0f;
            #pragma unroll
            for (int w = 0; w < 8; w++) s += red[tid][w];
            n_dev[tid] = DECAY_F * s + ALPHA_F * (float)BHW;
        }
    }
}

// ---------- kernel 2: distance sweep + argmin (vocab-split) ----------
// grid: (32, 8, 2) -> x: chunk of 256 positions, y: codebook, z: vocab half
// block: 128 threads, 2 positions per thread
// smem per vocab pair p (18 u64, 144B, 16B aligned):
//   [0..15]  (c[2p][j], c[2p+1][j]) for j=0..15
//   [16]     (0.5||c_2p||^2, 0.5||c_2p+1||^2)
//   [17]     pad
__global__ __launch_bounds__(128, 4) void vq_main(const float* __restrict__ z,
                                                  const float* __restrict__ cbs) {
    __shared__ __align__(16) unsigned long long sm2[PAIRS * 18];   // 36864 B
    float* smf = (float*)sm2;

    const int cb    = blockIdx.y;
    const int vbase = blockIdx.z * VHALF;
    const int tid   = threadIdx.x;

    // Load this block's half-codebook, interleaving vocab pairs
    {
        const float* src = cbs + ((size_t)cb * VOCAB + vbase) * CDIM;  // 8192 floats
        #pragma unroll
        for (int t = 0; t < 64; t++) {
            int i = tid + t * 128;            // coalesced read
            int v = i >> 4, j = i & 15;
            smf[(v >> 1) * 36 + 2 * j + (v & 1)] = src[i];
        }
    }
    __syncthreads();
    // h pairs
    #pragma unroll
    for (int t = 0; t < 4; t++) {
        int v = tid + t * 128;
        int p = v >> 1, o = v & 1;
        const float* r = smf + p * 36 + o;
        float s = 0.0f;
        #pragma unroll
        for (int j = 0; j < CDIM; j++) { float c = r[2 * j]; s += c * c; }
        smf[p * 36 + 32 + o] = 0.5f * s;
    }
    __syncthreads();

    // two positions per thread
    const int p0  = blockIdx.x * 256 + tid;
    const int p1  = p0 + 128;
    const int b   = p0 >> 10;
    const int hw0 = p0 & (HW - 1);
    const int hw1 = p1 & (HW - 1);

    const float* zb = z + (size_t)b * DCH * HW + (size_t)cb * CDIM * HW;

    unsigned long long zz0[CDIM], zz1[CDIM];
    #pragma unroll
    for (int j = 0; j < CDIM; j++) {
        float a = zb[j * HW + hw0];
        float c = zb[j * HW + hw1];
        zz0[j] = pack2(-a, -a);
        zz1[j] = pack2(-c, -c);
    }

    float best0 = 3.0e38f, best1 = 3.0e38f;
    int   bi0 = 0, bi1 = 0;

    #pragma unroll 2
    for (int p = 0; p < PAIRS; p++) {
        const ulonglong2* row = reinterpret_cast<const ulonglong2*>(sm2 + p * 18);
        const unsigned long long h = sm2[p * 18 + 16];
        ulonglong2 r0 = row[0], r1 = row[1], r2 = row[2], r3 = row[3];
        ulonglong2 r4 = row[4], r5 = row[5], r6 = row[6], r7 = row[7];

        unsigned long long a0, a1;
        a0 = fma2(zz0[0],  r0.x, h);  a1 = fma2(zz1[0],  r0.x, h);
        a0 = fma2(zz0[1],  r0.y, a0); a1 = fma2(zz1[1],  r0.y, a1);
        a0 = fma2(zz0[2],  r1.x, a0); a1 = fma2(zz1[2],  r1.x, a1);
        a0 = fma2(zz0[3],  r1.y, a0); a1 = fma2(zz1[3],  r1.y, a1);
        a0 = fma2(zz0[4],  r2.x, a0); a1 = fma2(zz1[4],  r2.x, a1);
        a0 = fma2(zz0[5],  r2.y, a0); a1 = fma2(zz1[5],  r2.y, a1);
        a0 = fma2(zz0[6],  r3.x, a0); a1 = fma2(zz1[6],  r3.x, a1);
        a0 = fma2(zz0[7],  r3.y, a0); a1 = fma2(zz1[7],  r3.y, a1);
        a0 = fma2(zz0[8],  r4.x, a0); a1 = fma2(zz1[8],  r4.x, a1);
        a0 = fma2(zz0[9],  r4.y, a0); a1 = fma2(zz1[9],  r4.y, a1);
        a0 = fma2(zz0[10], r5.x, a0); a1 = fma2(zz1[10], r5.x, a1);
        a0 = fma2(zz0[11], r5.y, a0); a1 = fma2(zz1[11], r5.y, a1);
        a0 = fma2(zz0[12], r6.x, a0); a1 = fma2(zz1[12], r6.x, a1);
        a0 = fma2(zz0[13], r6.y, a0); a1 = fma2(zz1[13], r6.y, a1);
        a0 = fma2(zz0[14], r7.x, a0); a1 = fma2(zz1[14], r7.x, a1);
        a0 = fma2(zz0[15], r7.y, a0); a1 = fma2(zz1[15], r7.y, a1);

        float sv0, sw0, sv1, sw1;
        unpack2(a0, sv0, sw0);
        unpack2(a1, sv1, sw1);
        const int ve = 2 * p, vo = 2 * p + 1;
        bool t;
        t = sv0 < best0; best0 = t ? sv0 : best0; bi0 = t ? ve : bi0;
        t = sw0 < best0; best0 = t ? sw0 : best0; bi0 = t ? vo : bi0;
        t = sv1 < best1; best1 = t ? sv1 : best1; bi1 = t ? ve : bi1;
        t = sw1 < best1; best1 = t ? sw1 : best1; bi1 = t ? vo : bi1;
    }

    // combine across vocab halves (ties -> smaller idx, matching argmin)
    unsigned long long* sc = vq_scratch + (size_t)cb * BHW;
    atomicMin(&sc[p0], ((unsigned long long)fkey(best0) << 32) | (unsigned)(vbase + bi0));
    atomicMin(&sc[p1], ((unsigned long long)fkey(best1) << 32) | (unsigned)(vbase + bi1));
}

// ---------- kernel 3: epilogue (quantize, indices, scatter, commitment) ----------
// grid: (64, 8), block 128, one position per thread
__global__ __launch_bounds__(128) void vq_epi(const float* __restrict__ z,
                                              const float* __restrict__ cbs,
                                              float* out) {
    const int cb  = blockIdx.y;
    const int tid = threadIdx.x;
    const int pos = blockIdx.x * 128 + tid;
    const int b   = pos >> 10;
    const int hw  = pos & (HW - 1);

    const int bi = (int)(unsigned)vq_scratch[(size_t)cb * BHW + pos];

    const float* crow = cbs + ((size_t)cb * VOCAB + bi) * CDIM;
    const float* zb   = z + (size_t)b * DCH * HW + (size_t)cb * CDIM * HW + hw;

    float* qout    = out + OFF_Q + (size_t)b * DCH * HW + (size_t)cb * CDIM * HW + hw;
    float* nweight = out + OFF_NW + ((size_t)cb * VOCAB + bi) * CDIM;

    float locc = 0.0f;
    #pragma unroll
    for (int j = 0; j < CDIM; j++) {
        const float zj = zb[(size_t)j * HW];
        const float cj = crow[j];
        qout[(size_t)j * HW] = zj + (cj - zj);       // match zq_st rounding
        const float d = zj - cj;
        locc += d * d;
        atomicAdd(&nweight[j], ALPHA_F * zj);
    }
    out[OFF_IDX + (size_t)b * (N_CB * HW) + (size_t)cb * HW + hw] = (float)bi;
    atomicAdd(out + OFF_NCNT + cb * VOCAB + bi, ALPHA_F);

    // commitment: shuffle reduce -> 1 atomic per block
    #pragma unroll
    for (int st = 16; st > 0; st >>= 1)
        locc += __shfl_xor_sync(0xFFFFFFFFu, locc, st);
    __shared__ float red[4];
    if ((tid & 31) == 0) red[tid >> 5] = locc;
    __syncthreads();
    if (tid == 0)
        atomicAdd(out + OFF_COMMIT,
                  (red[0] + red[1] + red[2] + red[3]) * (1.0f / (float)(BHW * N_CB * CDIM)));
}

// ---------- kernel 4: normalized codebook update (wide grid) ----------
// grid 512 x 256, one output element per thread
__global__ __launch_bounds__(256) void vq_final(float* out) {
    const int i  = blockIdx.x * 256 + threadIdx.x;    // 0 .. 131071
    const int cb = i >> 14;
    const int v  = (i >> 4) & (VOCAB - 1);

    const float cnt = out[OFF_NCNT + cb * VOCAB + v];
    const float n   = n_dev[cb];
    const float countv = (cnt + EPS_F) / (n + VOCAB * EPS_F) * n;
    out[OFF_NCB + i] = __fdividef(out[OFF_NW + i], countv);
}

extern "C" void kernel_launch(void* const* d_in, const int* in_sizes, int n_in,
                              void* d_out, int out_size) {
    const float* z   = (const float*)d_in[0];
    const float* cbs = (const float*)d_in[1];
    const float* ec  = (const float*)d_in[2];
    const float* ew  = (const float*)d_in[3];
    float* out = (float*)d_out;

    vq_init<<<512, 256>>>(ec, ew, out);
    dim3 gmain(32, N_CB, 2);
    vq_main<<<gmain, 128>>>(z, cbs);
    dim3 gepi(64, N_CB);
    vq_epi<<<gepi, 128>>>(z, cbs, out);
    vq_final<<<512, 256>>>(out);
}